// round 2
// baseline (speedup 1.0000x reference)
#include <cuda_runtime.h>
#include <cuda_bf16.h>
#include <stdint.h>

// Problem constants (fixed by the dataset instance)
#define NPTS 128
#define W    1024
#define L    1024
#define MTOT 2048   // 2 channels * W rows
#define SIGMA 32.0f

// Scratch (allocation-free rule: __device__ globals)
// gA layout: [k][m]  (k = point index 0..127, m = c*1024 + x), size 128*2048
// gB layout: [k][y]  size 128*1024
__device__ float gA[NPTS * MTOT];
__device__ float gB[NPTS * L];

// ---------------------------------------------------------------------------
// Kernel 1: build separable tables.
//   ex = exp(-(x - xc_n)^2 / (2 sigma^2));  A[n][c*1024+x] = ex * v[c][n]
//   ey = exp(-(y - yc_n)^2 / (2 sigma^2));  B[n][y] = ey
// grid (NPTS, W/256), block 256
// NOTE: coords are int32 (JAX x64 disabled downcasts jnp.int64 -> int32).
// ---------------------------------------------------------------------------
__global__ void precompute_kernel(const float* __restrict__ vecs,
                                  const int* __restrict__ xc,
                                  const int* __restrict__ yc)
{
    const int n = blockIdx.x;
    const int i = blockIdx.y * 256 + threadIdx.x;   // coordinate 0..1023
    const float inv2s2 = 1.0f / (2.0f * SIGMA * SIGMA);

    const float xcf = (float)xc[n];
    const float ycf = (float)yc[n];
    const float fi  = (float)i;

    const float dx = fi - xcf;
    const float ex = __expf(-dx * dx * inv2s2);
    const float dy = fi - ycf;
    const float ey = __expf(-dy * dy * inv2s2);

    const float v0 = vecs[n];
    const float v1 = vecs[NPTS + n];

    gA[n * MTOT + i]        = ex * v0;   // channel 0
    gA[n * MTOT + W + i]    = ex * v1;   // channel 1
    gB[n * L + i]           = ey;
}

// ---------------------------------------------------------------------------
// Kernel 2: GEMM  out[m][y] = sum_k gA[k][m] * gB[k][y]
// BM=128, BN=128, K=128 (fully shared-resident), 256 threads, 8x8 micro-tile,
// inner product via packed fma.rn.f32x2 (2 FMAs per FMA-pipe slot).
// ---------------------------------------------------------------------------

__device__ __forceinline__ unsigned long long pack_dup(float a) {
    unsigned long long r;
    asm("mov.b64 %0, {%1, %1};" : "=l"(r) : "f"(a));
    return r;
}
__device__ __forceinline__ void fma2(unsigned long long& acc,
                                     unsigned long long a,
                                     unsigned long long b) {
    asm("fma.rn.f32x2 %0, %1, %2, %0;" : "+l"(acc) : "l"(a), "l"(b));
}
__device__ __forceinline__ void unpack2(unsigned long long v, float& lo, float& hi) {
    asm("mov.b64 {%0, %1}, %2;" : "=f"(lo), "=f"(hi) : "l"(v));
}

#define BM 128
#define BN 128
#define KK 128

extern __shared__ float smem_dyn[];

__global__ void __launch_bounds__(256, 1)
gemm_kernel(float* __restrict__ out)
{
    float* As = smem_dyn;              // [KK][BM]
    float* Bs = smem_dyn + KK * BM;    // [KK][BN]

    const int tid    = threadIdx.x;
    const int m_base = blockIdx.y * BM;   // over MTOT = 2048 -> 16 blocks
    const int y_base = blockIdx.x * BN;   // over L    = 1024 -> 8 blocks

    // ---- load tiles: 128x128 floats each = 4096 float4, 256 threads -> 16 iters
    {
        const float4* Ag = (const float4*)(gA + m_base);   // row stride MTOT floats
        const float4* Bg = (const float4*)(gB + y_base);   // row stride L floats
        float4* As4 = (float4*)As;
        float4* Bs4 = (float4*)Bs;
#pragma unroll
        for (int i = 0; i < 16; i++) {
            const int idx4 = tid + i * 256;      // 0..4095
            const int k    = idx4 >> 5;          // 0..127
            const int q    = idx4 & 31;          // float4 col within row
            As4[k * (BM / 4) + q] = Ag[k * (MTOT / 4) + q];
            Bs4[k * (BN / 4) + q] = Bg[k * (L / 4) + q];
        }
    }
    __syncthreads();

    const int tx = tid & 15;   // y dir
    const int ty = tid >> 4;   // m dir
    const int m0 = ty * 8;
    const int y0 = tx * 8;

    unsigned long long acc[8][4];
#pragma unroll
    for (int im = 0; im < 8; im++)
#pragma unroll
        for (int j = 0; j < 4; j++) acc[im][j] = 0ull;

#pragma unroll 8
    for (int k = 0; k < KK; k++) {
        // a: 8 floats (broadcast-heavy LDS), b: 8 floats = 4 packed f32x2
        const float4 a_lo = *(const float4*)&As[k * BM + m0];
        const float4 a_hi = *(const float4*)&As[k * BM + m0 + 4];
        const ulonglong2 b01 = *(const ulonglong2*)&Bs[k * BN + y0];
        const ulonglong2 b23 = *(const ulonglong2*)&Bs[k * BN + y0 + 4];
        const unsigned long long pb[4] = { b01.x, b01.y, b23.x, b23.y };
        const float av[8] = { a_lo.x, a_lo.y, a_lo.z, a_lo.w,
                              a_hi.x, a_hi.y, a_hi.z, a_hi.w };
#pragma unroll
        for (int im = 0; im < 8; im++) {
            const unsigned long long aa = pack_dup(av[im]);
#pragma unroll
            for (int j = 0; j < 4; j++) fma2(acc[im][j], aa, pb[j]);
        }
    }

    // ---- epilogue: out[m][y], row stride L
#pragma unroll
    for (int im = 0; im < 8; im++) {
        const int row = m_base + m0 + im;
        float4 o0, o1;
        unpack2(acc[im][0], o0.x, o0.y);
        unpack2(acc[im][1], o0.z, o0.w);
        unpack2(acc[im][2], o1.x, o1.y);
        unpack2(acc[im][3], o1.z, o1.w);
        float* p = out + (size_t)row * L + y_base + y0;
        *(float4*)(p)     = o0;
        *(float4*)(p + 4) = o1;
    }
}

// ---------------------------------------------------------------------------
extern "C" void kernel_launch(void* const* d_in, const int* in_sizes, int n_in,
                              void* d_out, int out_size)
{
    const float* vecs = (const float*)d_in[0];   // [2,128] fp32
    const int*   xc   = (const int*)d_in[1];     // [128] int32 (JAX x64 off)
    const int*   yc   = (const int*)d_in[2];     // [128] int32
    float* out = (float*)d_out;                  // [1,2,1024,1024]

    (void)in_sizes; (void)n_in; (void)out_size;

    // Kernel 1: tables
    {
        dim3 grid(NPTS, W / 256);
        precompute_kernel<<<grid, 256>>>(vecs, xc, yc);
    }

    // Kernel 2: GEMM with 128 KB dynamic shared
    {
        const int smem_bytes = (KK * BM + KK * BN) * (int)sizeof(float); // 131072
        cudaFuncSetAttribute(gemm_kernel,
                             cudaFuncAttributeMaxDynamicSharedMemorySize,
                             smem_bytes);
        dim3 grid(L / BN, MTOT / BM);   // (8, 16) = 128 blocks
        gemm_kernel<<<grid, 256, smem_bytes>>>(out);
    }
}

// round 5
// speedup vs baseline: 1.5862x; 1.5862x over previous
#include <cuda_runtime.h>
#include <cuda_bf16.h>
#include <stdint.h>

// ---------------------------------------------------------------------------
// Problem constants
// ---------------------------------------------------------------------------
#define NPTS  128
#define W     1024
#define L     1024
#define MTOT  2048          // 2 channels * W
#define SIGMA 32.0f

// bf16 split GEMM: K' = 3*128  (Ah*Bh + Al*Bh + Ah*Bl; dropped Al*Bl ~ 2^-18)
#define KP   384
#define NKS  (KP / 16)      // 24 k-steps of 16
#define BM   128
#define BN   128

// ---------------------------------------------------------------------------
// Fragment-layout scratch tables (__device__ globals; no allocation).
// A stored as per-lane fragments of m16k16 tiles:
//   gAf[mt][ks][lane][reg(4)][half(2)]  (bf16)   mt = m/16, ks = k/16
// B stored as per-lane fragments of k16n8 tiles:
//   gBf[nt][ks][lane][reg(2)][half(2)]  (bf16)   nt = y/8
// ---------------------------------------------------------------------------
__device__ __align__(16) __nv_bfloat16 gAf[(MTOT / 16) * NKS * 32 * 8]; // 1.5 MB
__device__ __align__(16) __nv_bfloat16 gBf[(L / 8)    * NKS * 32 * 4]; // 768 KB

// mma.sync m16n8k16 .row.col fragment index math (PTX ISA layouts)
__device__ __forceinline__ void storeA(int m, int k, __nv_bfloat16 v) {
    const int mt = m >> 4, rm = m & 15;
    const int ks = k >> 4, rk = k & 15;
    const int lane = (rm & 7) * 4 + ((rk & 7) >> 1);
    const int reg  = (rm >> 3) + ((rk >> 3) << 1);   // a0:r0k0 a1:r8k0 a2:r0k8 a3:r8k8
    const int half = rk & 1;
    gAf[(((mt * NKS + ks) * 32 + lane) * 4 + reg) * 2 + half] = v;
}
__device__ __forceinline__ void storeB(int y, int k, __nv_bfloat16 v) {
    const int nt = y >> 3;
    const int ks = k >> 4, rk = k & 15;
    const int lane = (y & 7) * 4 + ((rk & 7) >> 1);
    const int reg  = rk >> 3;                        // b0:k0-7  b1:k8-15
    const int half = rk & 1;
    gBf[(((nt * NKS + ks) * 32 + lane) * 2 + reg) * 2 + half] = v;
}

// ---------------------------------------------------------------------------
// Kernel 1: separable tables with bf16 hi/lo split, written in fragment layout.
// grid = 1024 (coordinate i), block = 128 (point n)
// coords are int32 (JAX x64 disabled downcasts jnp.int64 -> int32)
// ---------------------------------------------------------------------------
__global__ void precompute_kernel(const float* __restrict__ vecs,
                                  const int* __restrict__ xc,
                                  const int* __restrict__ yc)
{
    const int i = blockIdx.x;      // coordinate 0..1023
    const int n = threadIdx.x;     // point 0..127
    const float inv2s2 = 1.0f / (2.0f * SIGMA * SIGMA);

    const float fi = (float)i;
    const float dx = fi - (float)xc[n];
    const float dy = fi - (float)yc[n];
    const float ex = __expf(-dx * dx * inv2s2);
    const float ey = __expf(-dy * dy * inv2s2);

    const float a0 = ex * vecs[n];          // channel 0
    const float a1 = ex * vecs[NPTS + n];   // channel 1

    const __nv_bfloat16 a0h = __float2bfloat16(a0);
    const __nv_bfloat16 a0l = __float2bfloat16(a0 - __bfloat162float(a0h));
    const __nv_bfloat16 a1h = __float2bfloat16(a1);
    const __nv_bfloat16 a1l = __float2bfloat16(a1 - __bfloat162float(a1h));
    const __nv_bfloat16 bh  = __float2bfloat16(ey);
    const __nv_bfloat16 bl  = __float2bfloat16(ey - __bfloat162float(bh));

    // A rows: ch0 -> m = i, ch1 -> m = W + i. K blocks: [Ah | Al | Ah]
    storeA(i,     n,       a0h);
    storeA(i,     128 + n, a0l);
    storeA(i,     256 + n, a0h);
    storeA(W + i, n,       a1h);
    storeA(W + i, 128 + n, a1l);
    storeA(W + i, 256 + n, a1h);
    // B row y = i. K blocks: [Bh | Bh | Bl]
    storeB(i, n,       bh);
    storeB(i, 128 + n, bh);
    storeB(i, 256 + n, bl);
}

// ---------------------------------------------------------------------------
// Kernel 2: warp-level HMMA GEMM  out[m][y] = sum_k' A''[m][k'] * B''[y][k']
// 128x128 tile per CTA, 8 warps in 2(m) x 4(n); warp tile 64x32.
// No smem: fragments are pre-laid-out in global (L2-resident).
// ---------------------------------------------------------------------------
__device__ __forceinline__ void mma16816(float* c, const uint32_t* a,
                                         const uint32_t* b) {
    asm volatile(
        "mma.sync.aligned.m16n8k16.row.col.f32.bf16.bf16.f32 "
        "{%0,%1,%2,%3}, {%4,%5,%6,%7}, {%8,%9}, {%0,%1,%2,%3};"
        : "+f"(c[0]), "+f"(c[1]), "+f"(c[2]), "+f"(c[3])
        : "r"(a[0]), "r"(a[1]), "r"(a[2]), "r"(a[3]),
          "r"(b[0]), "r"(b[1]));
}

__global__ void __launch_bounds__(256, 1)
gemm_mma_kernel(float* __restrict__ out)
{
    const int tid  = threadIdx.x;
    const int wid  = tid >> 5;
    const int lane = tid & 31;

    const int y_base = blockIdx.x * BN;     // 8 blocks
    const int m_base = blockIdx.y * BM;     // 16 blocks

    const int wm = wid >> 2;                // 0..1 (m dir)
    const int wn = wid & 3;                 // 0..3 (n dir)
    const int mt0 = ((m_base + wm * 64) >> 4);   // first of 4 m16 tiles
    const int nt0 = ((y_base + wn * 32) >> 3);   // first of 4 n8 tiles

    float acc[4][4][4] = {};                // [im][in][creg]

    const __nv_bfloat16* __restrict__ Af = gAf;
    const __nv_bfloat16* __restrict__ Bf = gBf;

#pragma unroll
    for (int ks = 0; ks < NKS; ks++) {
        uint4 a[4];
        uint2 b[4];
#pragma unroll
        for (int im = 0; im < 4; im++)
            a[im] = *(const uint4*)(Af +
                ((size_t)((mt0 + im) * NKS + ks) * 32 + lane) * 8);
#pragma unroll
        for (int in = 0; in < 4; in++)
            b[in] = *(const uint2*)(Bf +
                ((size_t)((nt0 + in) * NKS + ks) * 32 + lane) * 4);
#pragma unroll
        for (int im = 0; im < 4; im++)
#pragma unroll
            for (int in = 0; in < 4; in++)
                mma16816(acc[im][in], (const uint32_t*)&a[im],
                         (const uint32_t*)&b[in]);
    }

    // Epilogue: c0,c1 = (row g, cols 2t,2t+1); c2,c3 = (row g+8, same cols)
    const int g = lane >> 2;
    const int t = lane & 3;
#pragma unroll
    for (int im = 0; im < 4; im++) {
        const int row0 = m_base + wm * 64 + im * 16 + g;
#pragma unroll
        for (int in = 0; in < 4; in++) {
            const int col = y_base + wn * 32 + in * 8 + t * 2;
            float2* p0 = (float2*)(out + (size_t)row0 * L + col);
            float2* p1 = (float2*)(out + (size_t)(row0 + 8) * L + col);
            *p0 = make_float2(acc[im][in][0], acc[im][in][1]);
            *p1 = make_float2(acc[im][in][2], acc[im][in][3]);
        }
    }
}

// ---------------------------------------------------------------------------
extern "C" void kernel_launch(void* const* d_in, const int* in_sizes, int n_in,
                              void* d_out, int out_size)
{
    const float* vecs = (const float*)d_in[0];   // [2,128] fp32
    const int*   xc   = (const int*)d_in[1];     // [128] int32
    const int*   yc   = (const int*)d_in[2];     // [128] int32
    float* out = (float*)d_out;                  // [1,2,1024,1024] fp32

    (void)in_sizes; (void)n_in; (void)out_size;

    precompute_kernel<<<1024, 128>>>(vecs, xc, yc);

    dim3 grid(L / BN, MTOT / BM);   // (8, 16) = 128 CTAs, one wave
    gemm_mma_kernel<<<grid, 256>>>(out);
}

// round 6
// speedup vs baseline: 1.6140x; 1.0175x over previous
#include <cuda_runtime.h>
#include <cuda_bf16.h>
#include <stdint.h>

// ---------------------------------------------------------------------------
// Problem constants
// ---------------------------------------------------------------------------
#define NPTS  128
#define W     1024
#define L     1024
#define MTOT  2048          // 2 channels * W
#define SIGMA 32.0f

// bf16 split GEMM: K' = 3*128  (Ah*Bh + Al*Bh + Ah*Bl; dropped Al*Bl ~ 2^-18)
#define KP   384
#define NKS  (KP / 16)      // 24 k-steps of 16
#define BM   128
#define BN   128

// ---------------------------------------------------------------------------
// Fragment-layout scratch tables (__device__ globals; no allocation).
// A stored as per-lane fragments of m16k16 tiles:
//   gAf[mt][ks][lane][reg(4)][half(2)]  (bf16)   mt = m/16, ks = k/16
// B stored as per-lane fragments of k16n8 tiles:
//   gBf[nt][ks][lane][reg(2)][half(2)]  (bf16)   nt = y/8
// ---------------------------------------------------------------------------
__device__ __align__(16) __nv_bfloat16 gAf[(MTOT / 16) * NKS * 32 * 8]; // 1.5 MB
__device__ __align__(16) __nv_bfloat16 gBf[(L / 8)    * NKS * 32 * 4]; // 768 KB

// mma.sync m16n8k16 .row.col fragment index math (PTX ISA layouts)
__device__ __forceinline__ void storeA(int m, int k, __nv_bfloat16 v) {
    const int mt = m >> 4, rm = m & 15;
    const int ks = k >> 4, rk = k & 15;
    const int lane = (rm & 7) * 4 + ((rk & 7) >> 1);
    const int reg  = (rm >> 3) + ((rk >> 3) << 1);
    const int half = rk & 1;
    gAf[(((mt * NKS + ks) * 32 + lane) * 4 + reg) * 2 + half] = v;
}
__device__ __forceinline__ void storeB(int y, int k, __nv_bfloat16 v) {
    const int nt = y >> 3;
    const int ks = k >> 4, rk = k & 15;
    const int lane = (y & 7) * 4 + ((rk & 7) >> 1);
    const int reg  = rk >> 3;
    const int half = rk & 1;
    gBf[(((nt * NKS + ks) * 32 + lane) * 2 + reg) * 2 + half] = v;
}

// ---------------------------------------------------------------------------
// Kernel 1: separable tables with bf16 hi/lo split, written in fragment layout.
// grid = 1024 (coordinate i), block = 128 (point n)
// coords are int32 (JAX x64 disabled downcasts jnp.int64 -> int32)
// ---------------------------------------------------------------------------
__global__ void precompute_kernel(const float* __restrict__ vecs,
                                  const int* __restrict__ xc,
                                  const int* __restrict__ yc)
{
    const int i = blockIdx.x;      // coordinate 0..1023
    const int n = threadIdx.x;     // point 0..127
    const float inv2s2 = 1.0f / (2.0f * SIGMA * SIGMA);

    const float fi = (float)i;
    const float dx = fi - (float)xc[n];
    const float dy = fi - (float)yc[n];
    const float ex = __expf(-dx * dx * inv2s2);
    const float ey = __expf(-dy * dy * inv2s2);

    const float a0 = ex * vecs[n];          // channel 0
    const float a1 = ex * vecs[NPTS + n];   // channel 1

    const __nv_bfloat16 a0h = __float2bfloat16(a0);
    const __nv_bfloat16 a0l = __float2bfloat16(a0 - __bfloat162float(a0h));
    const __nv_bfloat16 a1h = __float2bfloat16(a1);
    const __nv_bfloat16 a1l = __float2bfloat16(a1 - __bfloat162float(a1h));
    const __nv_bfloat16 bh  = __float2bfloat16(ey);
    const __nv_bfloat16 bl  = __float2bfloat16(ey - __bfloat162float(bh));

    // A rows: ch0 -> m = i, ch1 -> m = W + i. K blocks: [Ah | Al | Ah]
    storeA(i,     n,       a0h);
    storeA(i,     128 + n, a0l);
    storeA(i,     256 + n, a0h);
    storeA(W + i, n,       a1h);
    storeA(W + i, 128 + n, a1l);
    storeA(W + i, 256 + n, a1h);
    // B row y = i. K blocks: [Bh | Bh | Bl]
    storeB(i, n,       bh);
    storeB(i, 128 + n, bh);
    storeB(i, 256 + n, bl);
}

// ---------------------------------------------------------------------------
// Kernel 2: warp-level HMMA GEMM  out[m][y] = sum_k' A''[m][k'] * B''[y][k']
// 128x128 tile per CTA, 512 threads = 16 warps in 4(m) x 4(n);
// warp tile 32x32 (2 m16 x 4 n8). Software-pipelined fragment LDGs.
// ---------------------------------------------------------------------------
__device__ __forceinline__ void mma16816(float* c, const uint32_t* a,
                                         const uint32_t* b) {
    asm volatile(
        "mma.sync.aligned.m16n8k16.row.col.f32.bf16.bf16.f32 "
        "{%0,%1,%2,%3}, {%4,%5,%6,%7}, {%8,%9}, {%0,%1,%2,%3};"
        : "+f"(c[0]), "+f"(c[1]), "+f"(c[2]), "+f"(c[3])
        : "r"(a[0]), "r"(a[1]), "r"(a[2]), "r"(a[3]),
          "r"(b[0]), "r"(b[1]));
}

__global__ void __launch_bounds__(512, 1)
gemm_mma_kernel(float* __restrict__ out)
{
    const int tid  = threadIdx.x;
    const int wid  = tid >> 5;
    const int lane = tid & 31;

    const int y_base = blockIdx.x * BN;     // 8 blocks
    const int m_base = blockIdx.y * BM;     // 16 blocks

    const int wm = wid >> 2;                // 0..3 (m dir)
    const int wn = wid & 3;                 // 0..3 (n dir)
    const int mt0 = ((m_base + wm * 32) >> 4);   // first of 2 m16 tiles
    const int nt0 = ((y_base + wn * 32) >> 3);   // first of 4 n8 tiles

    float acc[2][4][4] = {};                // [im][in][creg]

    const __nv_bfloat16* __restrict__ Af = gAf;
    const __nv_bfloat16* __restrict__ Bf = gBf;

    // per-lane fragment base pointers (advance by 32*frag per ks)
    const uint4* pa0 = (const uint4*)(Af + ((size_t)((mt0 + 0) * NKS) * 32 + lane) * 8);
    const uint4* pa1 = (const uint4*)(Af + ((size_t)((mt0 + 1) * NKS) * 32 + lane) * 8);
    const uint2* pb0 = (const uint2*)(Bf + ((size_t)((nt0 + 0) * NKS) * 32 + lane) * 4);
    const uint2* pb1 = (const uint2*)(Bf + ((size_t)((nt0 + 1) * NKS) * 32 + lane) * 4);
    const uint2* pb2 = (const uint2*)(Bf + ((size_t)((nt0 + 2) * NKS) * 32 + lane) * 4);
    const uint2* pb3 = (const uint2*)(Bf + ((size_t)((nt0 + 3) * NKS) * 32 + lane) * 4);

    uint4 a_cur[2];
    uint2 b_cur[4];
    a_cur[0] = pa0[0];  a_cur[1] = pa1[0];
    b_cur[0] = pb0[0];  b_cur[1] = pb1[0];
    b_cur[2] = pb2[0];  b_cur[3] = pb3[0];

#pragma unroll
    for (int ks = 0; ks < NKS; ks++) {
        uint4 a_nxt[2];
        uint2 b_nxt[4];
        if (ks + 1 < NKS) {
            const int s = (ks + 1) * 32;
            a_nxt[0] = pa0[s];  a_nxt[1] = pa1[s];
            b_nxt[0] = pb0[s];  b_nxt[1] = pb1[s];
            b_nxt[2] = pb2[s];  b_nxt[3] = pb3[s];
        }
#pragma unroll
        for (int im = 0; im < 2; im++)
#pragma unroll
            for (int in = 0; in < 4; in++)
                mma16816(acc[im][in], (const uint32_t*)&a_cur[im],
                         (const uint32_t*)&b_cur[in]);
        if (ks + 1 < NKS) {
            a_cur[0] = a_nxt[0];  a_cur[1] = a_nxt[1];
            b_cur[0] = b_nxt[0];  b_cur[1] = b_nxt[1];
            b_cur[2] = b_nxt[2];  b_cur[3] = b_nxt[3];
        }
    }

    // Epilogue: c0,c1 = (row g, cols 2t,2t+1); c2,c3 = (row g+8)
    const int g = lane >> 2;
    const int t = lane & 3;
#pragma unroll
    for (int im = 0; im < 2; im++) {
        const int row0 = m_base + wm * 32 + im * 16 + g;
#pragma unroll
        for (int in = 0; in < 4; in++) {
            const int col = y_base + wn * 32 + in * 8 + t * 2;
            float2* p0 = (float2*)(out + (size_t)row0 * L + col);
            float2* p1 = (float2*)(out + (size_t)(row0 + 8) * L + col);
            *p0 = make_float2(acc[im][in][0], acc[im][in][1]);
            *p1 = make_float2(acc[im][in][2], acc[im][in][3]);
        }
    }
}

// ---------------------------------------------------------------------------
extern "C" void kernel_launch(void* const* d_in, const int* in_sizes, int n_in,
                              void* d_out, int out_size)
{
    const float* vecs = (const float*)d_in[0];   // [2,128] fp32
    const int*   xc   = (const int*)d_in[1];     // [128] int32
    const int*   yc   = (const int*)d_in[2];     // [128] int32
    float* out = (float*)d_out;                  // [1,2,1024,1024] fp32

    (void)in_sizes; (void)n_in; (void)out_size;

    precompute_kernel<<<1024, 128>>>(vecs, xc, yc);

    dim3 grid(L / BN, MTOT / BM);   // (8, 16) = 128 CTAs, one wave
    gemm_mma_kernel<<<grid, 512>>>(out);
}